// round 10
// baseline (speedup 1.0000x reference)
#include <cuda_runtime.h>
#include <math.h>

#define BSZ   16
#define GR    52
#define HH    256
#define WW    256
#define HW    (HH * WW)
#define CL    4                   // cluster size: 4 CTAs per plane
#define QROWS (HH / CL)           // 64 rows per CTA
#define QHW   (QROWS * WW)        // 16384 elems per quarter
#define QHW4  (QHW / 4)           // 4096 float4
#define NT    512
#define NW    (NT / 32)           // 16 warps
#define ITERS (QHW4 / NT)         // 8 float4 iters per thread
#define GRPSZ 4
#define NGRP  (ITERS / GRPSZ)     // 2
#define MBYTES (QHW * 4)          // 65536 B fp32 quarter-plane

#define CLUSTER_SYNC_() do { \
    asm volatile("barrier.cluster.arrive.aligned;" ::: "memory"); \
    asm volatile("barrier.cluster.wait.aligned;" ::: "memory"); } while (0)

__device__ __forceinline__ float ld_peer_f32(unsigned saddr, unsigned peer) {
    unsigned ra; float v;
    asm("mapa.shared::cluster.u32 %0, %1, %2;" : "=r"(ra) : "r"(saddr), "r"(peer));
    asm volatile("ld.shared::cluster.f32 %0, [%1];" : "=f"(v) : "r"(ra));
    return v;
}

__global__ __launch_bounds__(NT, 2) __cluster_dims__(CL, 1, 1)
void prm_kernel(const float* __restrict__ x,
                const float* __restrict__ wgt,
                const float* __restrict__ bias,
                const float* __restrict__ one,
                const float* __restrict__ zero,
                const float* __restrict__ theta,
                const float* __restrict__ scale,
                float* __restrict__ out)
{
    extern __shared__ __align__(16) float xs[];    // fp32 quarter-plane [64][256]
    __shared__ __align__(16) float glut[QROWS];    // own 64 rows (raw -> folded)
    __shared__ __align__(16) float hlut[WW];       // all 256 cols
    __shared__ float red[6][NW];
    __shared__ float rv[NW]; __shared__ int rix[NW];
    __shared__ __align__(16) float xchA[4];        // s, s2, bv, bi(bits)
    __shared__ __align__(16) float xchB[6];        // sweep partials
    __shared__ float bc[8];

    const int      plane = blockIdx.x / CL;        // plane = b*GR + g
    const unsigned rank  = blockIdx.x & (CL - 1);  // which quarter (rows 64*rank..)
    const int      g     = plane % GR;
    const int tid  = threadIdx.x;
    const int lane = tid & 31;
    const int wid  = tid >> 5;
    const int rsub = tid >> 6;                     // row offset in each 8-row stripe
    const int csub = tid & 63;                     // col group

    const float4* x4 = (const float4*)x + (size_t)plane * (HW / 4) + (size_t)rank * QHW4;
    float4*       o4 = (float4*)out     + (size_t)plane * (HW / 4) + (size_t)rank * QHW4;
    float4*       xs4 = (float4*)xs;

    // ================= Pass 1: only DRAM read; x -> fp32 smem ================
    float bv = -3.402823466e38f;
    int   bi = 0x7fffffff;                         // GLOBAL linear index in plane
    float s0 = 0.f, s1 = 0.f, q0a = 0.f, q1a = 0.f;

    #pragma unroll
    for (int grp = 0; grp < NGRP; ++grp) {
        float4 v[GRPSZ];
        #pragma unroll
        for (int j = 0; j < GRPSZ; ++j)
            v[j] = x4[(grp * GRPSZ + j) * NT + tid];
        #pragma unroll
        for (int j = 0; j < GRPSZ; ++j) {
            int idx4 = (grp * GRPSZ + j) * NT + tid;
            float4 t = v[j];
            xs4[idx4] = t;                         // fp32 copy stays on the SM
            int i0 = (int)(rank * QHW) + (idx4 << 2);
            s0  += t.x + t.y;             s1  += t.z + t.w;
            q0a += t.x * t.x + t.y * t.y; q1a += t.z * t.z + t.w * t.w;
            float m = fmaxf(fmaxf(t.x, t.y), fmaxf(t.z, t.w));
            if (m > bv) {                          // first occurrence
                bv = m;
                bi = i0 + (t.x == m ? 0 : (t.y == m ? 1 : (t.z == m ? 2 : 3)));
            }
        }
    }

    // block reduce s/s2/argmax
    float s = s0 + s1, s2 = q0a + q1a;
    #pragma unroll
    for (int o = 16; o; o >>= 1) {
        s  += __shfl_down_sync(0xffffffffu, s,  o);
        s2 += __shfl_down_sync(0xffffffffu, s2, o);
        float ov = __shfl_down_sync(0xffffffffu, bv, o);
        int   oi = __shfl_down_sync(0xffffffffu, bi, o);
        if (ov > bv || (ov == bv && oi < bi)) { bv = ov; bi = oi; }
    }
    if (lane == 0) { red[0][wid] = s; red[1][wid] = s2; rv[wid] = bv; rix[wid] = bi; }
    __syncthreads();
    if (wid == 0) {
        s  = (lane < NW) ? red[0][lane] : 0.f;
        s2 = (lane < NW) ? red[1][lane] : 0.f;
        bv = (lane < NW) ? rv[lane] : -3.402823466e38f;
        bi = (lane < NW) ? rix[lane] : 0x7fffffff;
        #pragma unroll
        for (int o = 16; o; o >>= 1) {
            s  += __shfl_down_sync(0xffffffffu, s,  o);
            s2 += __shfl_down_sync(0xffffffffu, s2, o);
            float ov = __shfl_down_sync(0xffffffffu, bv, o);
            int   oi = __shfl_down_sync(0xffffffffu, bi, o);
            if (ov > bv || (ov == bv && oi < bi)) { bv = ov; bi = oi; }
        }
        if (lane == 0) {
            xchA[0] = s; xchA[1] = s2; xchA[2] = bv; xchA[3] = __int_as_float(bi);
        }
    }
    __syncthreads();
    CLUSTER_SYNC_();                               // publish xchA cluster-wide

    // -------- combine quarter partials (every CTA computes identically) -------
    if (tid == 0) {
        unsigned a0 = (unsigned)__cvta_generic_to_shared(&xchA[0]);
        float Sx = xchA[0], Sx2 = xchA[1];
        float gbv = xchA[2]; int gbi = __float_as_int(xchA[3]);
        #pragma unroll
        for (int j = 1; j < CL; ++j) {
            unsigned pr = (rank + j) & (CL - 1);
            float ps  = ld_peer_f32(a0,      pr);
            float ps2 = ld_peer_f32(a0 + 4,  pr);
            float pbv = ld_peer_f32(a0 + 8,  pr);
            int   pbi = __float_as_int(ld_peer_f32(a0 + 12, pr));
            Sx += ps; Sx2 += ps2;
            if (pbv > gbv || (pbv == gbv && pbi < gbi)) { gbv = pbv; gbi = pbi; }
        }
        bc[0] = (float)(gbi >> 8);                 // qrow (global)
        bc[1] = (float)(gbi & 255);                // qcol
        bc[2] = gbv * zero[g];                     // A
        bc[3] = Sx * (1.0f / (float)HW) * one[g];  // B
        bc[4] = Sx;
        bc[5] = Sx2;
    }
    __syncthreads();

    // ================= Gaussian LUTs (raw) ====================================
    {
        float sigma  = scale[0];
        float ln     = -logf(sigma) - 0.91893853320467274f;
        float inv2s2 = 0.5f / (sigma * sigma);
        if (tid < QROWS) {                         // own global rows
            float r = (float)(tid + QROWS * (int)rank);
            float d = fabsf(r - bc[0]) * theta[0];
            glut[tid] = __expf(ln - d * d * inv2s2);
        } else if (tid < QROWS + WW) {
            int   c = tid - QROWS;
            float d = fabsf((float)c - bc[1]) * theta[1];
            hlut[c] = __expf(ln - d * d * inv2s2);
        }
    }
    __syncthreads();

    // ===== smem sweep over own fp32 quarter: 6 LUT-weighted stats =============
    // warp w: local rows [4w, 4w+4); lane covers cols [8*lane, 8*lane+8)
    float t3 = 0.f, t4 = 0.f, t5 = 0.f, t6 = 0.f, t7 = 0.f, t12 = 0.f;
    {
        float4 ha  = *(const float4*)&hlut[8 * lane];
        float4 hb  = *(const float4*)&hlut[8 * lane + 4];
        float4 ha2 = { ha.x * ha.x, ha.y * ha.y, ha.z * ha.z, ha.w * ha.w };
        float4 hb2 = { hb.x * hb.x, hb.y * hb.y, hb.z * hb.z, hb.w * hb.w };
        #pragma unroll
        for (int r4 = 0; r4 < 4; ++r4) {
            int r = 4 * wid + r4;
            const float4* rowp = (const float4*)&xs[256 * r + 8 * lane];
            float4 u = rowp[0], w4 = rowp[1];
            float x0 = u.x * u.x,  x1 = u.y * u.y,  x2 = u.z * u.z,  x3 = u.w * u.w;
            float x4v = w4.x * w4.x, x5 = w4.y * w4.y, x6 = w4.z * w4.z, x7 = w4.w * w4.w;
            float sx   = (u.x + u.y) + (u.z + u.w) + (w4.x + w4.y) + (w4.z + w4.w);
            float sxh  = u.x * ha.x + u.y * ha.y + u.z * ha.z + u.w * ha.w
                       + w4.x * hb.x + w4.y * hb.y + w4.z * hb.z + w4.w * hb.w;
            float sm   = (x0 + x1) + (x2 + x3) + (x4v + x5) + (x6 + x7);
            float smh  = x0 * ha.x + x1 * ha.y + x2 * ha.z + x3 * ha.w
                       + x4v * hb.x + x5 * hb.y + x6 * hb.z + x7 * hb.w;
            float smh2 = x0 * ha2.x + x1 * ha2.y + x2 * ha2.z + x3 * ha2.w
                       + x4v * hb2.x + x5 * hb2.y + x6 * hb2.z + x7 * hb2.w;
            float gr = glut[r];
            t3  += gr * sm;
            t4  += smh;
            t5  += gr * gr * sm;
            t6  += smh2;
            t7  += gr * smh;
            t12 += gr * sx + sxh;
        }
    }
    #pragma unroll
    for (int o = 16; o; o >>= 1) {
        t3  += __shfl_down_sync(0xffffffffu, t3,  o);
        t4  += __shfl_down_sync(0xffffffffu, t4,  o);
        t5  += __shfl_down_sync(0xffffffffu, t5,  o);
        t6  += __shfl_down_sync(0xffffffffu, t6,  o);
        t7  += __shfl_down_sync(0xffffffffu, t7,  o);
        t12 += __shfl_down_sync(0xffffffffu, t12, o);
    }
    if (lane == 0) {
        red[0][wid] = t3; red[1][wid] = t4; red[2][wid] = t5;
        red[3][wid] = t6; red[4][wid] = t7; red[5][wid] = t12;
    }
    __syncthreads();
    if (wid == 0) {
        t3  = (lane < NW) ? red[0][lane] : 0.f;
        t4  = (lane < NW) ? red[1][lane] : 0.f;
        t5  = (lane < NW) ? red[2][lane] : 0.f;
        t6  = (lane < NW) ? red[3][lane] : 0.f;
        t7  = (lane < NW) ? red[4][lane] : 0.f;
        t12 = (lane < NW) ? red[5][lane] : 0.f;
        #pragma unroll
        for (int o = 16; o; o >>= 1) {
            t3  += __shfl_down_sync(0xffffffffu, t3,  o);
            t4  += __shfl_down_sync(0xffffffffu, t4,  o);
            t5  += __shfl_down_sync(0xffffffffu, t5,  o);
            t6  += __shfl_down_sync(0xffffffffu, t6,  o);
            t7  += __shfl_down_sync(0xffffffffu, t7,  o);
            t12 += __shfl_down_sync(0xffffffffu, t12, o);
        }
        if (lane == 0) {
            xchB[0] = t3; xchB[1] = t4; xchB[2] = t5;
            xchB[3] = t6; xchB[4] = t7; xchB[5] = t12;
        }
    }
    __syncthreads();
    CLUSTER_SYNC_();                               // publish xchB cluster-wide

    if (tid == 0) {
        unsigned b0 = (unsigned)__cvta_generic_to_shared(&xchB[0]);
        float T3 = xchB[0], T4 = xchB[1], T5 = xchB[2];
        float T6 = xchB[3], T7 = xchB[4], T12 = xchB[5];
        #pragma unroll
        for (int j = 1; j < CL; ++j) {
            unsigned pr = (rank + j) & (CL - 1);
            T3  += ld_peer_f32(b0,      pr);
            T4  += ld_peer_f32(b0 + 4,  pr);
            T5  += ld_peer_f32(b0 + 8,  pr);
            T6  += ld_peer_f32(b0 + 12, pr);
            T7  += ld_peer_f32(b0 + 16, pr);
            T12 += ld_peer_f32(b0 + 20, pr);
        }
        float A = bc[2], B = bc[3], Sx = bc[4], Sx2 = bc[5];
        float sxe   = 0.5f  * A * T12;
        float sx2e  = 0.5f  * A * (T3 + T4);
        float sx2e2 = 0.25f * A * A * (T5 + T6 + 2.f * T7);
        float Ssim  = sxe + B * Sx;
        float Ssim2 = sx2e2 + 2.f * B * sx2e + B * B * Sx2;
        float mean  = Ssim * (1.0f / (float)HW);
        float var   = (Ssim2 - Ssim * Ssim * (1.0f / (float)HW)) * (1.0f / (float)(HW - 1));
        float sd    = sqrtf(fmaxf(var, 0.f)) + 1e-5f;
        float k1    = wgt[g] / sd;
        bc[0] = 0.5f * A * k1;                     // LUT scale
        bc[1] = B * k1;                            // folded into G
        bc[2] = bias[g] - mean * k1;               // c0
    }
    __syncthreads();

    // fold constants into LUTs: G = 0.5*A*k1*g + B*k1 ; H = 0.5*A*k1*h
    {
        float sA = bc[0], Bk = bc[1];
        if (tid < QROWS)                 glut[tid] = fmaf(glut[tid], sA, Bk);
        else if (tid < QROWS + WW)       hlut[tid - QROWS] *= sA;
    }
    __syncthreads();

    // ================= Pass 2: gated output, x read from smem ================
    {
        float c0 = bc[2];
        float4 Hc = *(const float4*)&hlut[4 * csub];   // cols fixed per thread
        #pragma unroll
        for (int it = 0; it < ITERS; ++it) {
            int idx4 = it * NT + tid;
            float4 t = xs4[idx4];
            float gr = glut[8 * it + rsub];            // local row
            float t0  = fmaf(t.x, gr + Hc.x, c0);
            float t1  = fmaf(t.y, gr + Hc.y, c0);
            float t2  = fmaf(t.z, gr + Hc.z, c0);
            float t3v = fmaf(t.w, gr + Hc.w, c0);
            float4 o;
            o.x = __fdividef(t.x, 1.f + __expf(-t0));
            o.y = __fdividef(t.y, 1.f + __expf(-t1));
            o.z = __fdividef(t.z, 1.f + __expf(-t2));
            o.w = __fdividef(t.w, 1.f + __expf(-t3v));
            __stcs(&o4[idx4], o);
        }
    }
    CLUSTER_SYNC_();   // peers may still read my xch slots; hold smem until all done
}

extern "C" void kernel_launch(void* const* d_in, const int* in_sizes, int n_in,
                              void* d_out, int out_size)
{
    const float* x     = (const float*)d_in[0];
    const float* wgt   = (const float*)d_in[1];
    const float* bias  = (const float*)d_in[2];
    const float* one   = (const float*)d_in[3];
    const float* zero  = (const float*)d_in[4];
    const float* theta = (const float*)d_in[5];
    const float* scale = (const float*)d_in[6];
    float* out = (float*)d_out;

    cudaFuncSetAttribute(prm_kernel, cudaFuncAttributeMaxDynamicSharedMemorySize, MBYTES);
    prm_kernel<<<BSZ * GR * CL, NT, MBYTES>>>(x, wgt, bias, one, zero, theta, scale, out);
}

// round 14
// speedup vs baseline: 1.4523x; 1.4523x over previous
#include <cuda_runtime.h>
#include <math.h>

#define BSZ   16
#define GR    52
#define HH    256
#define WW    256
#define HW    (HH * WW)
#define NPL   (BSZ * GR)          // 832 planes
#define CL    4                   // quarters per plane
#define QROWS (HH / CL)           // 64 rows per quarter
#define QHW   (QROWS * WW)        // 16384 elems
#define QHW4  (QHW / 4)           // 4096 float4
#define NQ    (NPL * CL)          // 3328 quarters
#define NT    512
#define NW    (NT / 32)           // 16 warps
#define ITERS (QHW4 / NT)         // 8 float4 iters per thread
#define GRPSZ 4
#define NGRP  (ITERS / GRPSZ)     // 2
#define NCTAS 296                 // 148 SMs x 2 — all resident (296 % 4 == 0)
#define MBYTES (QHW * 4)          // 64 KB fp32 quarter

// tiny per-launch scratch (static device memory — no allocation)
__device__ float g_pA[NQ * 4];    // per-quarter: s, s2, bv, bi
__device__ float g_pB[NQ * 6];    // per-quarter: t3,t4,t5,t6,t7,t12
__device__ int   g_cnt1[NPL];
__device__ int   g_cnt2[NPL];

__global__ void reset_kernel()
{
    int i = threadIdx.x + blockIdx.x * blockDim.x;
    if (i < NPL) { g_cnt1[i] = 0; g_cnt2[i] = 0; }
}

__global__ __launch_bounds__(NT, 2)
void prm_kernel(const float* __restrict__ x,
                const float* __restrict__ wgt,
                const float* __restrict__ bias,
                const float* __restrict__ one,
                const float* __restrict__ zero,
                const float* __restrict__ theta,
                const float* __restrict__ scale,
                float* __restrict__ out)
{
    extern __shared__ __align__(16) float xs[];    // fp32 quarter [64][256]
    __shared__ __align__(16) float glut[QROWS];
    __shared__ __align__(16) float hlut[WW];
    __shared__ float red[6][NW];
    __shared__ float rv[NW]; __shared__ int rix[NW];
    __shared__ float bc[8];

    const int tid  = threadIdx.x;
    const int lane = tid & 31;
    const int wid  = tid >> 5;
    const int rsub = tid >> 6;                     // row offset per 8-row stripe
    const int csub = tid & 63;                     // col group
    float4* xs4 = (float4*)xs;

    for (int q = blockIdx.x; q < NQ; q += NCTAS) {
        const int plane = q >> 2;
        const int rank  = q & 3;
        const int g     = plane % GR;
        const float4* x4 = (const float4*)x + (size_t)plane * (HW / 4) + (size_t)rank * QHW4;
        float4*       o4 = (float4*)out     + (size_t)plane * (HW / 4) + (size_t)rank * QHW4;

        // ============ Pass 1: only DRAM read; x -> fp32 smem ================
        float bv = -3.402823466e38f;
        int   bi = 0x7fffffff;
        float s0 = 0.f, s1 = 0.f, q0a = 0.f, q1a = 0.f;

        #pragma unroll
        for (int grp = 0; grp < NGRP; ++grp) {
            float4 v[GRPSZ];
            #pragma unroll
            for (int j = 0; j < GRPSZ; ++j)
                v[j] = x4[(grp * GRPSZ + j) * NT + tid];
            #pragma unroll
            for (int j = 0; j < GRPSZ; ++j) {
                int idx4 = (grp * GRPSZ + j) * NT + tid;
                float4 t = v[j];
                xs4[idx4] = t;
                int i0 = rank * QHW + (idx4 << 2);     // global index in plane
                s0  += t.x + t.y;             s1  += t.z + t.w;
                q0a += t.x * t.x + t.y * t.y; q1a += t.z * t.z + t.w * t.w;
                float m = fmaxf(fmaxf(t.x, t.y), fmaxf(t.z, t.w));
                if (m > bv) {                          // first occurrence
                    bv = m;
                    bi = i0 + (t.x == m ? 0 : (t.y == m ? 1 : (t.z == m ? 2 : 3)));
                }
            }
        }

        float s = s0 + s1, s2 = q0a + q1a;
        #pragma unroll
        for (int o = 16; o; o >>= 1) {
            s  += __shfl_down_sync(0xffffffffu, s,  o);
            s2 += __shfl_down_sync(0xffffffffu, s2, o);
            float ov = __shfl_down_sync(0xffffffffu, bv, o);
            int   oi = __shfl_down_sync(0xffffffffu, bi, o);
            if (ov > bv || (ov == bv && oi < bi)) { bv = ov; bi = oi; }
        }
        if (lane == 0) { red[0][wid] = s; red[1][wid] = s2; rv[wid] = bv; rix[wid] = bi; }
        __syncthreads();
        if (wid == 0) {
            s  = (lane < NW) ? red[0][lane] : 0.f;
            s2 = (lane < NW) ? red[1][lane] : 0.f;
            bv = (lane < NW) ? rv[lane] : -3.402823466e38f;
            bi = (lane < NW) ? rix[lane] : 0x7fffffff;
            #pragma unroll
            for (int o = 16; o; o >>= 1) {
                s  += __shfl_down_sync(0xffffffffu, s,  o);
                s2 += __shfl_down_sync(0xffffffffu, s2, o);
                float ov = __shfl_down_sync(0xffffffffu, bv, o);
                int   oi = __shfl_down_sync(0xffffffffu, bi, o);
                if (ov > bv || (ov == bv && oi < bi)) { bv = ov; bi = oi; }
            }
            if (lane == 0) {
                // publish quarter partials, arrive, spin for plane peers, combine
                float* slot = &g_pA[q << 2];
                slot[0] = s; slot[1] = s2; slot[2] = bv; slot[3] = __int_as_float(bi);
                __threadfence();
                atomicAdd(&g_cnt1[plane], 1);
                volatile int* c1 = &g_cnt1[plane];
                while (*c1 < 4) __nanosleep(40);
                __threadfence();
                float Sx = 0.f, Sx2 = 0.f, gbv = -3.402823466e38f; int gbi = 0x7fffffff;
                #pragma unroll
                for (int j = 0; j < 4; ++j) {
                    const volatile float* ps = &g_pA[(((plane << 2) + j)) << 2];
                    float a = ps[0], b2 = ps[1], c = ps[2];
                    int   d = __float_as_int(ps[3]);
                    Sx += a; Sx2 += b2;
                    if (c > gbv || (c == gbv && d < gbi)) { gbv = c; gbi = d; }
                }
                bc[0] = (float)(gbi >> 8);                 // qrow
                bc[1] = (float)(gbi & 255);                // qcol
                bc[2] = gbv * zero[g];                     // A
                bc[3] = Sx * (1.0f / (float)HW) * one[g];  // B
                bc[4] = Sx;
                bc[5] = Sx2;
            }
        }
        __syncthreads();

        // ============ Gaussian LUTs (raw) ===================================
        {
            float sigma  = scale[0];
            float ln     = -logf(sigma) - 0.91893853320467274f;
            float inv2s2 = 0.5f / (sigma * sigma);
            if (tid < QROWS) {
                float r = (float)(tid + QROWS * rank);
                float d = fabsf(r - bc[0]) * theta[0];
                glut[tid] = __expf(ln - d * d * inv2s2);
            } else if (tid < QROWS + WW) {
                int   c = tid - QROWS;
                float d = fabsf((float)c - bc[1]) * theta[1];
                hlut[c] = __expf(ln - d * d * inv2s2);
            }
        }
        __syncthreads();

        // ===== smem sweep: 6 LUT-weighted stats over own fp32 quarter =======
        float t3 = 0.f, t4 = 0.f, t5 = 0.f, t6 = 0.f, t7 = 0.f, t12 = 0.f;
        {
            float4 ha  = *(const float4*)&hlut[8 * lane];
            float4 hb  = *(const float4*)&hlut[8 * lane + 4];
            float4 ha2 = { ha.x * ha.x, ha.y * ha.y, ha.z * ha.z, ha.w * ha.w };
            float4 hb2 = { hb.x * hb.x, hb.y * hb.y, hb.z * hb.z, hb.w * hb.w };
            #pragma unroll
            for (int r4 = 0; r4 < 4; ++r4) {
                int r = 4 * wid + r4;
                const float4* rowp = (const float4*)&xs[256 * r + 8 * lane];
                float4 u = rowp[0], w4 = rowp[1];
                float x0 = u.x * u.x,  x1 = u.y * u.y,  x2 = u.z * u.z,  x3 = u.w * u.w;
                float x4v = w4.x * w4.x, x5 = w4.y * w4.y, x6 = w4.z * w4.z, x7 = w4.w * w4.w;
                float sx   = (u.x + u.y) + (u.z + u.w) + (w4.x + w4.y) + (w4.z + w4.w);
                float sxh  = u.x * ha.x + u.y * ha.y + u.z * ha.z + u.w * ha.w
                           + w4.x * hb.x + w4.y * hb.y + w4.z * hb.z + w4.w * hb.w;
                float sm   = (x0 + x1) + (x2 + x3) + (x4v + x5) + (x6 + x7);
                float smh  = x0 * ha.x + x1 * ha.y + x2 * ha.z + x3 * ha.w
                           + x4v * hb.x + x5 * hb.y + x6 * hb.z + x7 * hb.w;
                float smh2 = x0 * ha2.x + x1 * ha2.y + x2 * ha2.z + x3 * ha2.w
                           + x4v * hb2.x + x5 * hb2.y + x6 * hb2.z + x7 * hb2.w;
                float gr = glut[r];
                t3  += gr * sm;
                t4  += smh;
                t5  += gr * gr * sm;
                t6  += smh2;
                t7  += gr * smh;
                t12 += gr * sx + sxh;
            }
        }
        #pragma unroll
        for (int o = 16; o; o >>= 1) {
            t3  += __shfl_down_sync(0xffffffffu, t3,  o);
            t4  += __shfl_down_sync(0xffffffffu, t4,  o);
            t5  += __shfl_down_sync(0xffffffffu, t5,  o);
            t6  += __shfl_down_sync(0xffffffffu, t6,  o);
            t7  += __shfl_down_sync(0xffffffffu, t7,  o);
            t12 += __shfl_down_sync(0xffffffffu, t12, o);
        }
        if (lane == 0) {
            red[0][wid] = t3; red[1][wid] = t4; red[2][wid] = t5;
            red[3][wid] = t6; red[4][wid] = t7; red[5][wid] = t12;
        }
        __syncthreads();
        if (wid == 0) {
            t3  = (lane < NW) ? red[0][lane] : 0.f;
            t4  = (lane < NW) ? red[1][lane] : 0.f;
            t5  = (lane < NW) ? red[2][lane] : 0.f;
            t6  = (lane < NW) ? red[3][lane] : 0.f;
            t7  = (lane < NW) ? red[4][lane] : 0.f;
            t12 = (lane < NW) ? red[5][lane] : 0.f;
            #pragma unroll
            for (int o = 16; o; o >>= 1) {
                t3  += __shfl_down_sync(0xffffffffu, t3,  o);
                t4  += __shfl_down_sync(0xffffffffu, t4,  o);
                t5  += __shfl_down_sync(0xffffffffu, t5,  o);
                t6  += __shfl_down_sync(0xffffffffu, t6,  o);
                t7  += __shfl_down_sync(0xffffffffu, t7,  o);
                t12 += __shfl_down_sync(0xffffffffu, t12, o);
            }
            if (lane == 0) {
                float* slot = &g_pB[q * 6];
                slot[0] = t3; slot[1] = t4; slot[2] = t5;
                slot[3] = t6; slot[4] = t7; slot[5] = t12;
                __threadfence();
                atomicAdd(&g_cnt2[plane], 1);
                volatile int* c2 = &g_cnt2[plane];
                while (*c2 < 4) __nanosleep(40);
                __threadfence();
                float T3 = 0.f, T4 = 0.f, T5 = 0.f, T6 = 0.f, T7 = 0.f, T12 = 0.f;
                #pragma unroll
                for (int j = 0; j < 4; ++j) {
                    const volatile float* ps = &g_pB[((plane << 2) + j) * 6];
                    T3 += ps[0]; T4 += ps[1]; T5 += ps[2];
                    T6 += ps[3]; T7 += ps[4]; T12 += ps[5];
                }
                float A = bc[2], B = bc[3], Sx = bc[4], Sx2 = bc[5];
                float sxe   = 0.5f  * A * T12;
                float sx2e  = 0.5f  * A * (T3 + T4);
                float sx2e2 = 0.25f * A * A * (T5 + T6 + 2.f * T7);
                float Ssim  = sxe + B * Sx;
                float Ssim2 = sx2e2 + 2.f * B * sx2e + B * B * Sx2;
                float mean  = Ssim * (1.0f / (float)HW);
                float var   = (Ssim2 - Ssim * Ssim * (1.0f / (float)HW)) * (1.0f / (float)(HW - 1));
                float sd    = sqrtf(fmaxf(var, 0.f)) + 1e-5f;
                float k1    = wgt[g] / sd;
                bc[0] = 0.5f * A * k1;                 // LUT scale
                bc[1] = B * k1;                        // folded into G
                bc[2] = bias[g] - mean * k1;           // c0
            }
        }
        __syncthreads();

        // fold constants into LUTs: G = 0.5*A*k1*g + B*k1 ; H = 0.5*A*k1*h
        {
            float sA = bc[0], Bk = bc[1];
            if (tid < QROWS)                glut[tid] = fmaf(glut[tid], sA, Bk);
            else if (tid < QROWS + WW)      hlut[tid - QROWS] *= sA;
        }
        __syncthreads();

        // ============ Pass 2: gated output, x read from smem ================
        {
            float c0 = bc[2];
            float4 Hc = *(const float4*)&hlut[4 * csub];
            #pragma unroll
            for (int it = 0; it < ITERS; ++it) {
                int idx4 = it * NT + tid;
                float4 t = xs4[idx4];
                float gr = glut[8 * it + rsub];
                float t0  = fmaf(t.x, gr + Hc.x, c0);
                float t1  = fmaf(t.y, gr + Hc.y, c0);
                float t2  = fmaf(t.z, gr + Hc.z, c0);
                float t3v = fmaf(t.w, gr + Hc.w, c0);
                float4 o;
                o.x = __fdividef(t.x, 1.f + __expf(-t0));
                o.y = __fdividef(t.y, 1.f + __expf(-t1));
                o.z = __fdividef(t.z, 1.f + __expf(-t2));
                o.w = __fdividef(t.w, 1.f + __expf(-t3v));
                __stcs(&o4[idx4], o);
            }
        }
        __syncthreads();   // protect smem (xs/luts/bc) before next round reuses it
    }
}

extern "C" void kernel_launch(void* const* d_in, const int* in_sizes, int n_in,
                              void* d_out, int out_size)
{
    const float* x     = (const float*)d_in[0];
    const float* wgt   = (const float*)d_in[1];
    const float* bias  = (const float*)d_in[2];
    const float* one   = (const float*)d_in[3];
    const float* zero  = (const float*)d_in[4];
    const float* theta = (const float*)d_in[5];
    const float* scale = (const float*)d_in[6];
    float* out = (float*)d_out;

    reset_kernel<<<1, 1024>>>();
    cudaFuncSetAttribute(prm_kernel, cudaFuncAttributeMaxDynamicSharedMemorySize, MBYTES);
    prm_kernel<<<NCTAS, NT, MBYTES>>>(x, wgt, bias, one, zero, theta, scale, out);
}